// round 5
// baseline (speedup 1.0000x reference)
#include <cuda_runtime.h>
#include <cuda_bf16.h>
#include <math.h>
#include <stdint.h>

#define SEQ     4096
#define DMODEL  2048
#define DHEAD   128
#define NH      16
#define NKV     4
#define NCOLS   3072
#define KDIM    2048

// ---------------- scratch ----------------
__device__ __align__(256) float g_bcat[NCOLS];
__device__ __align__(256) __nv_bfloat16 g_xhi[SEQ * DMODEL];
__device__ __align__(256) __nv_bfloat16 g_xlo[SEQ * DMODEL];
__device__ __align__(256) __nv_bfloat16 g_zhi[SEQ * DMODEL];
__device__ __align__(256) __nv_bfloat16 g_zlo[SEQ * DMODEL];
__device__ __align__(256) __nv_bfloat16 g_Wthi[NCOLS * KDIM];
__device__ __align__(256) __nv_bfloat16 g_Wtlo[NCOLS * KDIM];
__device__ __align__(256) __nv_bfloat16 g_WOthi[DMODEL * KDIM];
__device__ __align__(256) __nv_bfloat16 g_WOtlo[DMODEL * KDIM];
__device__ __align__(256) __nv_bfloat16 g_qbhi[SEQ * DMODEL];
__device__ __align__(256) __nv_bfloat16 g_qblo[SEQ * DMODEL];
__device__ __align__(256) __nv_bfloat16 g_kbhi[NKV * SEQ * DHEAD];
__device__ __align__(256) __nv_bfloat16 g_kblo[NKV * SEQ * DHEAD];
__device__ __align__(256) __nv_bfloat16 g_vthi[NKV * DHEAD * SEQ];
__device__ __align__(256) __nv_bfloat16 g_vtlo[NKV * DHEAD * SEQ];
__device__ __align__(256) float g_rcos[SEQ * 64];
__device__ __align__(256) float g_rsin[SEQ * 64];

// ---------------- helpers ----------------
__device__ __forceinline__ uint32_t smem_u32(const void* p) {
    uint32_t a;
    asm("{ .reg .u64 t; cvta.to.shared.u64 t, %1; cvt.u32.u64 %0, t; }" : "=r"(a) : "l"(p));
    return a;
}
__device__ __forceinline__ void cp16(uint32_t s, const void* g) {
    asm volatile("cp.async.cg.shared.global [%0], [%1], 16;" :: "r"(s), "l"(g));
}
#define CP_COMMIT() asm volatile("cp.async.commit_group;" ::: "memory")
__device__ __forceinline__ void ldsm4(uint32_t* r, uint32_t addr) {
    asm volatile("ldmatrix.sync.aligned.m8n8.x4.shared.b16 {%0,%1,%2,%3}, [%4];"
        : "=r"(r[0]), "=r"(r[1]), "=r"(r[2]), "=r"(r[3]) : "r"(addr));
}
__device__ __forceinline__ void mma_bf16(float* d, const uint32_t* a, const uint32_t* b) {
    asm volatile("mma.sync.aligned.m16n8k16.row.col.f32.bf16.bf16.f32 "
        "{%0,%1,%2,%3}, {%4,%5,%6,%7}, {%8,%9}, {%0,%1,%2,%3};"
        : "+f"(d[0]), "+f"(d[1]), "+f"(d[2]), "+f"(d[3])
        : "r"(a[0]), "r"(a[1]), "r"(a[2]), "r"(a[3]), "r"(b[0]), "r"(b[1]));
}
__device__ __forceinline__ float ex2f(float x) {
    float y; asm("ex2.approx.ftz.f32 %0, %1;" : "=f"(y) : "f"(x)); return y;
}
__device__ __forceinline__ void split2(float p0, float p1, uint32_t& hi, uint32_t& lo) {
    __nv_bfloat16 h0 = __float2bfloat16(p0), h1 = __float2bfloat16(p1);
    float r0 = p0 - __bfloat162float(h0), r1 = p1 - __bfloat162float(h1);
    __nv_bfloat16 e0 = __float2bfloat16(r0), e1 = __float2bfloat16(r1);
    hi = ((uint32_t)__bfloat16_as_ushort(h1) << 16) | (uint32_t)__bfloat16_as_ushort(h0);
    lo = ((uint32_t)__bfloat16_as_ushort(e1) << 16) | (uint32_t)__bfloat16_as_ushort(e0);
}
__device__ __forceinline__ void split1(float v, __nv_bfloat16& h, __nv_bfloat16& l) {
    h = __float2bfloat16(v);
    l = __float2bfloat16(v - __bfloat162float(h));
}
__device__ __forceinline__ void store_pair(__nv_bfloat16* hi, __nv_bfloat16* lo,
                                           size_t off, float v0, float v1) {
    __nv_bfloat16 h0, l0, h1, l1;
    split1(v0, h0, l0);
    split1(v1, h1, l1);
    *(__nv_bfloat162*)(hi + off) = __nv_bfloat162(h0, h1);
    *(__nv_bfloat162*)(lo + off) = __nv_bfloat162(l0, l1);
}
#define SWZ(off) ((off) ^ (((off) >> 3) & 0x70))

// ---------------- repack QKV weights + bias + rotary table (merged) ----------------
#define REP_BLOCKS ((NCOLS * KDIM) / 256)   // 24576
__global__ void repack_wqkv_rot(const float* __restrict__ WQ, const float* __restrict__ WK,
                                const float* __restrict__ WV, const float* __restrict__ bQ,
                                const float* __restrict__ bK, const float* __restrict__ bV) {
    if (blockIdx.x >= REP_BLOCKS) {
        int idx = (blockIdx.x - REP_BLOCKS) * 256 + threadIdx.x;
        if (idx >= SEQ * 64) return;
        int j = idx & 63, s = idx >> 6;
        double dfreq = pow(10000.0, -(double)j / 64.0);
        float freq = (float)dfreq;
        float angle = (float)s * freq;
        double da = (double)angle;
        g_rcos[idx] = (float)cos(da);
        g_rsin[idx] = (float)sin(da);
        return;
    }
    int idx = blockIdx.x * 256 + threadIdx.x;
    if (idx < NCOLS) {
        float b;
        if      (idx < 2048) b = bQ[idx];
        else if (idx < 2560) b = bK[idx - 2048];
        else                 b = bV[idx - 2560];
        g_bcat[idx] = b;
    }
    int n = idx >> 11;
    int k = idx & 2047;
    float v;
    if (n < 2048) {
        int head = n >> 7, h = n & 127;
        v = WQ[((size_t)head * KDIM + k) * DHEAD + h];
    } else if (n < 2560) {
        int head = (n - 2048) >> 7, h = n & 127;
        v = WK[((size_t)head * KDIM + k) * DHEAD + h];
    } else {
        int head = (n - 2560) >> 7, h = n & 127;
        v = WV[((size_t)head * KDIM + k) * DHEAD + h];
    }
    __nv_bfloat16 hi, lo;
    split1(v, hi, lo);
    g_Wthi[idx] = hi;
    g_Wtlo[idx] = lo;
}

__global__ void repack_wo(const float* __restrict__ WO) {
    int idx = blockIdx.x * blockDim.x + threadIdx.x;
    if (idx >= DMODEL * KDIM) return;
    int k = idx >> 11;
    int m = idx & 2047;
    __nv_bfloat16 hi, lo;
    split1(WO[idx], hi, lo);
    g_WOthi[(size_t)m * KDIM + k] = hi;
    g_WOtlo[(size_t)m * KDIM + k] = lo;
}

__global__ void split_f32(const float* __restrict__ src, __nv_bfloat16* __restrict__ hi,
                          __nv_bfloat16* __restrict__ lo, int n) {
    int i = blockIdx.x * blockDim.x + threadIdx.x;
    if (i >= n) return;
    __nv_bfloat16 h, l;
    split1(src[i], h, l);
    hi[i] = h;
    lo[i] = l;
}

// ---------------- 3-stage mma.sync bf16x3 GEMM ----------------
// EPI=0: C = A*B^T + bias (fp32 out). EPI=1: fused QKV epilogue (rotary + splits).
#define BM 128
#define BN 128
#define BKT 64
#define MATB 16384
#define BUFB (4 * MATB)        // 64 KB per stage
#define GSMEM (3 * BUFB)       // 192 KB
#define NSTG (KDIM / BKT)      // 32

__device__ __forceinline__ void load_stage(uint32_t bb, int k0, int m0, int n0, int tid,
                                           const __nv_bfloat16* Ahi, const __nv_bfloat16* Alo,
                                           const __nv_bfloat16* Bhi, const __nv_bfloat16* Blo) {
    #pragma unroll
    for (int i = 0; i < 4; i++) {
        int c = tid + i * 256;
        int r = c >> 3, ch = c & 7;
        uint32_t so = bb + SWZ(r * 128 + ch * 16);
        size_t ga = (size_t)(m0 + r) * KDIM + k0 + ch * 8;
        size_t gb = (size_t)(n0 + r) * KDIM + k0 + ch * 8;
        cp16(so,            Ahi + ga);
        cp16(so + MATB,     Alo + ga);
        cp16(so + 2 * MATB, Bhi + gb);
        cp16(so + 3 * MATB, Blo + gb);
    }
}

template<int EPI>
__global__ __launch_bounds__(256, 1) void gemm3(
    const __nv_bfloat16* __restrict__ Ahi, const __nv_bfloat16* __restrict__ Alo,
    const __nv_bfloat16* __restrict__ Bhi, const __nv_bfloat16* __restrict__ Blo,
    const float* __restrict__ bias, float* __restrict__ C, int N)
{
    extern __shared__ char sm[];
    const uint32_t smb = smem_u32(sm);
    const int tid = threadIdx.x;
    const int wid = tid >> 5, lid = tid & 31;
    const int m0 = blockIdx.x * BM, n0 = blockIdx.y * BN;
    const int wm = (wid & 1) * 64;
    const int wn = (wid >> 1) * 32;

    float acc[4][4][4];
    #pragma unroll
    for (int i = 0; i < 4; i++)
        #pragma unroll
        for (int j = 0; j < 4; j++)
            #pragma unroll
            for (int k = 0; k < 4; k++) acc[i][j][k] = 0.f;

    const int arow = lid & 15;
    const int asel = (lid >> 4) * 16;
    const int brow = ((lid >> 4) << 3) + (lid & 7);
    const int bsel = ((lid >> 3) & 1) * 16;

    load_stage(smb, 0, m0, n0, tid, Ahi, Alo, Bhi, Blo);
    CP_COMMIT();
    load_stage(smb + BUFB, BKT, m0, n0, tid, Ahi, Alo, Bhi, Blo);
    CP_COMMIT();

    for (int s = 0; s < NSTG; s++) {
        if (s + 1 < NSTG) asm volatile("cp.async.wait_group 1;" ::: "memory");
        else              asm volatile("cp.async.wait_group 0;" ::: "memory");
        __syncthreads();
        if (s + 2 < NSTG) {
            load_stage(smb + ((s + 2) % 3) * BUFB, (s + 2) * BKT, m0, n0, tid,
                       Ahi, Alo, Bhi, Blo);
            CP_COMMIT();
        }
        uint32_t bb = smb + (s % 3) * BUFB;
        #pragma unroll
        for (int kk = 0; kk < 4; kk++) {
            uint32_t ah[4][4], al[4][4];
            #pragma unroll
            for (int ms = 0; ms < 4; ms++) {
                uint32_t off = SWZ((wm + ms * 16 + arow) * 128 + kk * 32 + asel);
                ldsm4(ah[ms], bb + off);
                ldsm4(al[ms], bb + MATB + off);
            }
            uint32_t bh[2][4], bl[2][4];
            #pragma unroll
            for (int ns = 0; ns < 2; ns++) {
                uint32_t off = SWZ((wn + ns * 16 + brow) * 128 + kk * 32 + bsel);
                ldsm4(bh[ns], bb + 2 * MATB + off);
                ldsm4(bl[ns], bb + 3 * MATB + off);
            }
            #pragma unroll
            for (int ms = 0; ms < 4; ms++)
                #pragma unroll
                for (int n8 = 0; n8 < 4; n8++) {
                    const uint32_t* ph = &bh[n8 >> 1][(n8 & 1) * 2];
                    const uint32_t* pl = &bl[n8 >> 1][(n8 & 1) * 2];
                    mma_bf16(acc[ms][n8], ah[ms], ph);
                    mma_bf16(acc[ms][n8], ah[ms], pl);
                    mma_bf16(acc[ms][n8], al[ms], ph);
                }
        }
    }

    const int erow = lid >> 2, ecol = (lid & 3) * 2;
    #pragma unroll
    for (int ms = 0; ms < 4; ms++) {
        int r0 = m0 + wm + ms * 16 + erow;
        #pragma unroll
        for (int n8 = 0; n8 < 4; n8++) {
            int c = n0 + wn + n8 * 8 + ecol;
            float2 bv = *(const float2*)&bias[c];
            float a00 = acc[ms][n8][0] + bv.x, a01 = acc[ms][n8][1] + bv.y;
            float a10 = acc[ms][n8][2] + bv.x, a11 = acc[ms][n8][3] + bv.y;
            if (EPI == 0) {
                *(float2*)&C[(size_t)r0 * N + c]       = make_float2(a00, a01);
                *(float2*)&C[(size_t)(r0 + 8) * N + c] = make_float2(a10, a11);
            } else {
                if (n0 < 2048) {                       // Q: rotary + split
                    int j = (c & 127) >> 1;
                    float c0 = g_rcos[r0 * 64 + j],      s0 = g_rsin[r0 * 64 + j];
                    float c1 = g_rcos[(r0 + 8) * 64 + j], s1 = g_rsin[(r0 + 8) * 64 + j];
                    store_pair(g_qbhi, g_qblo, (size_t)r0 * DMODEL + c,
                               a00 * c0 - a01 * s0, a00 * s0 + a01 * c0);
                    store_pair(g_qbhi, g_qblo, (size_t)(r0 + 8) * DMODEL + c,
                               a10 * c1 - a11 * s1, a10 * s1 + a11 * c1);
                } else if (n0 < 2560) {                // K: rotary + split, [kvh][s][dh]
                    int kvh = (c - 2048) >> 7, dh = c & 127, j = dh >> 1;
                    float c0 = g_rcos[r0 * 64 + j],      s0 = g_rsin[r0 * 64 + j];
                    float c1 = g_rcos[(r0 + 8) * 64 + j], s1 = g_rsin[(r0 + 8) * 64 + j];
                    size_t base = ((size_t)kvh * SEQ + r0) * DHEAD + dh;
                    store_pair(g_kbhi, g_kblo, base,
                               a00 * c0 - a01 * s0, a00 * s0 + a01 * c0);
                    store_pair(g_kbhi, g_kblo, base + 8 * DHEAD,
                               a10 * c1 - a11 * s1, a10 * s1 + a11 * c1);
                } else {                               // V: split + transpose [kvh][dh][s]
                    int kvh = (c - 2560) >> 7, dh = c & 127;
                    size_t b0 = ((size_t)kvh * DHEAD + dh) * SEQ;
                    size_t b1 = b0 + SEQ;
                    __nv_bfloat16 h, l;
                    split1(a00, h, l); g_vthi[b0 + r0] = h;     g_vtlo[b0 + r0] = l;
                    split1(a01, h, l); g_vthi[b1 + r0] = h;     g_vtlo[b1 + r0] = l;
                    split1(a10, h, l); g_vthi[b0 + r0 + 8] = h; g_vtlo[b0 + r0 + 8] = l;
                    split1(a11, h, l); g_vthi[b1 + r0 + 8] = h; g_vtlo[b1 + r0 + 8] = l;
                }
            }
        }
    }
}

// ---------------- flash attention, 3-stage KV pipeline, Q in registers ----------------
// smem: 3 x 64KB buffers. Buffer for KV stage kb = (kb+1)%3; Q staged in buf0 once.
// per buffer: K 4x[64][64] at +sb*8192 (hi0,hi1,lo0,lo1), Vt 2x[128][64] at +32768.
#define ATT_SMEM 196608

__device__ __forceinline__ void load_kv(uint32_t dst, int kv0, int tid,
                                        const __nv_bfloat16* khi, const __nv_bfloat16* klo,
                                        const __nv_bfloat16* vhi, const __nv_bfloat16* vlo) {
    #pragma unroll
    for (int sb = 0; sb < 4; sb++) {
        int isl = sb >> 1, b = sb & 1;
        const __nv_bfloat16* src = isl ? klo : khi;
        #pragma unroll
        for (int i = 0; i < 2; i++) {
            int c = tid + i * 256;
            int r = c >> 3, ch = c & 7;
            cp16(dst + sb * 8192 + SWZ(r * 128 + ch * 16),
                 src + (size_t)(kv0 + r) * DHEAD + b * 64 + ch * 8);
        }
    }
    #pragma unroll
    for (int isl = 0; isl < 2; isl++) {
        const __nv_bfloat16* src = isl ? vlo : vhi;
        #pragma unroll
        for (int i = 0; i < 4; i++) {
            int c = tid + i * 256;
            int d = c >> 3, ch = c & 7;
            cp16(dst + 32768 + isl * 16384 + SWZ(d * 128 + ch * 16),
                 src + (size_t)d * SEQ + kv0 + ch * 8);
        }
    }
}

__global__ __launch_bounds__(256, 1) void attn_mma() {
    extern __shared__ char sm[];
    const uint32_t smb = smem_u32(sm);
    const int tid = threadIdx.x;
    const int wid = tid >> 5, lid = tid & 31;
    const int qb = (int)(gridDim.x - 1) - (int)blockIdx.x;
    const int h = blockIdx.y;
    const int kvh = h >> 2;
    const int q0 = qb * 128;
    const int nkv = 2 * qb + 2;
    const int w16 = wid * 16;

    const int arow = lid & 15;
    const int asel = (lid >> 4) * 16;
    const int brow = ((lid >> 4) << 3) + (lid & 7);
    const int bsel = ((lid >> 3) & 1) * 16;

    const __nv_bfloat16* khi = g_kbhi + (size_t)kvh * SEQ * DHEAD;
    const __nv_bfloat16* klo = g_kblo + (size_t)kvh * SEQ * DHEAD;
    const __nv_bfloat16* vhi = g_vthi + (size_t)kvh * DHEAD * SEQ;
    const __nv_bfloat16* vlo = g_vtlo + (size_t)kvh * DHEAD * SEQ;

    // stage Q into buf0, KV(0) into buf1
    #pragma unroll
    for (int sb = 0; sb < 4; sb++) {
        int isl = sb >> 1, b = sb & 1;
        const __nv_bfloat16* src = isl ? g_qblo : g_qbhi;
        #pragma unroll
        for (int i = 0; i < 4; i++) {
            int c = tid + i * 256;
            int r = c >> 3, ch = c & 7;
            cp16(smb + sb * 16384 + SWZ(r * 128 + ch * 16),
                 src + (size_t)(q0 + r) * DMODEL + h * DHEAD + b * 64 + ch * 8);
        }
    }
    CP_COMMIT();
    load_kv(smb + 65536, 0, tid, khi, klo, vhi, vlo);
    CP_COMMIT();
    asm volatile("cp.async.wait_group 1;" ::: "memory");
    __syncthreads();

    // Q fragments -> registers (each warp reads only its own 16 rows)
    uint32_t qh[8][4], ql[8][4];
    #pragma unroll
    for (int kk = 0; kk < 8; kk++) {
        int b = kk >> 2, koff = (kk & 3) * 32;
        uint32_t off = smb + b * 16384 + SWZ((w16 + arow) * 128 + koff + asel);
        ldsm4(qh[kk], off);
        ldsm4(ql[kk], off + 32768);
    }
    if (nkv > 1) {
        load_kv(smb + 2 * 65536, 64, tid, khi, klo, vhi, vlo);
        CP_COMMIT();
    }

    float oacc[16][4];
    #pragma unroll
    for (int i = 0; i < 16; i++)
        #pragma unroll
        for (int j = 0; j < 4; j++) oacc[i][j] = 0.f;
    float m2[2] = {-1e30f, -1e30f};
    float l2[2] = {0.f, 0.f};
    const float KE = (float)(1.4426950408889634 / 11.313708498984761);

    for (int kb = 0; kb < nkv; kb++) {
        if (kb + 1 < nkv) asm volatile("cp.async.wait_group 1;" ::: "memory");
        else              asm volatile("cp.async.wait_group 0;" ::: "memory");
        __syncthreads();
        if (kb + 2 < nkv) {
            load_kv(smb + ((kb + 3) % 3) * 65536, (kb + 2) * 64, tid, khi, klo, vhi, vlo);
            CP_COMMIT();
        }
        const uint32_t kvb = smb + ((kb + 1) % 3) * 65536;
        const uint32_t vbase = kvb + 32768;

        // ---- S = Q K^T ----
        float sacc[8][4];
        #pragma unroll
        for (int i = 0; i < 8; i++)
            #pragma unroll
            for (int j = 0; j < 4; j++) sacc[i][j] = 0.f;

        #pragma unroll
        for (int kk = 0; kk < 8; kk++) {
            int b = kk >> 2, koff = (kk & 3) * 32;
            #pragma unroll
            for (int ns = 0; ns < 4; ns++) {
                uint32_t bh[4], bl[4];
                uint32_t boff = kvb + b * 8192 + SWZ((ns * 16 + brow) * 128 + koff + bsel);
                ldsm4(bh, boff);
                ldsm4(bl, boff + 16384);
                mma_bf16(sacc[2 * ns],     qh[kk], bh);     mma_bf16(sacc[2 * ns],     qh[kk], bl);     mma_bf16(sacc[2 * ns],     ql[kk], bh);
                mma_bf16(sacc[2 * ns + 1], qh[kk], bh + 2); mma_bf16(sacc[2 * ns + 1], qh[kk], bl + 2); mma_bf16(sacc[2 * ns + 1], ql[kk], bh + 2);
            }
        }

        // ---- online softmax ----
        const int kv0 = kb * 64;
        const bool dodiag = (kb >= nkv - 2);
        #pragma unroll
        for (int g = 0; g < 2; g++) {
            int grow = q0 + w16 + (lid >> 2) + g * 8;
            if (dodiag) {
                #pragma unroll
                for (int n8 = 0; n8 < 8; n8++) {
                    int col = kv0 + n8 * 8 + (lid & 3) * 2;
                    if (col > grow)     sacc[n8][2 * g]     = -1e30f;
                    if (col + 1 > grow) sacc[n8][2 * g + 1] = -1e30f;
                }
            }
            float mt = -1e30f;
            #pragma unroll
            for (int n8 = 0; n8 < 8; n8++)
                mt = fmaxf(mt, fmaxf(sacc[n8][2 * g], sacc[n8][2 * g + 1]));
            mt = fmaxf(mt, __shfl_xor_sync(0xffffffffu, mt, 1));
            mt = fmaxf(mt, __shfl_xor_sync(0xffffffffu, mt, 2));
            float mnew = fmaxf(m2[g], mt);
            float alpha = ex2f((m2[g] - mnew) * KE);
            float ls = 0.f;
            #pragma unroll
            for (int n8 = 0; n8 < 8; n8++) {
                float p0 = ex2f((sacc[n8][2 * g]     - mnew) * KE);
                float p1 = ex2f((sacc[n8][2 * g + 1] - mnew) * KE);
                sacc[n8][2 * g] = p0; sacc[n8][2 * g + 1] = p1;
                ls += p0 + p1;
            }
            ls += __shfl_xor_sync(0xffffffffu, ls, 1);
            ls += __shfl_xor_sync(0xffffffffu, ls, 2);
            l2[g] = l2[g] * alpha + ls;
            m2[g] = mnew;
            #pragma unroll
            for (int t = 0; t < 16; t++) {
                oacc[t][2 * g]     *= alpha;
                oacc[t][2 * g + 1] *= alpha;
            }
        }

        // ---- O += P V ----
        #pragma unroll
        for (int t = 0; t < 4; t++) {
            uint32_t pa[4], pl[4];
            split2(sacc[2 * t][0],     sacc[2 * t][1],     pa[0], pl[0]);
            split2(sacc[2 * t][2],     sacc[2 * t][3],     pa[1], pl[1]);
            split2(sacc[2 * t + 1][0], sacc[2 * t + 1][1], pa[2], pl[2]);
            split2(sacc[2 * t + 1][2], sacc[2 * t + 1][3], pa[3], pl[3]);
            #pragma unroll
            for (int ns = 0; ns < 8; ns++) {
                uint32_t vh[4], vl[4];
                uint32_t voff = vbase + SWZ((ns * 16 + brow) * 128 + t * 32 + bsel);
                ldsm4(vh, voff);
                ldsm4(vl, voff + 16384);
                mma_bf16(oacc[2 * ns],     pa, vh);     mma_bf16(oacc[2 * ns],     pa, vl);     mma_bf16(oacc[2 * ns],     pl, vh);
                mma_bf16(oacc[2 * ns + 1], pa, vh + 2); mma_bf16(oacc[2 * ns + 1], pa, vl + 2); mma_bf16(oacc[2 * ns + 1], pl, vh + 2);
            }
        }
    }

    // ---- epilogue ----
    float inv0 = 1.f / l2[0], inv1 = 1.f / l2[1];
    int r0 = q0 + w16 + (lid >> 2);
    int cb = h * DHEAD + (lid & 3) * 2;
    #pragma unroll
    for (int n8 = 0; n8 < 16; n8++) {
        int col = cb + n8 * 8;
        store_pair(g_zhi, g_zlo, (size_t)r0 * DMODEL + col,
                   oacc[n8][0] * inv0, oacc[n8][1] * inv0);
        store_pair(g_zhi, g_zlo, (size_t)(r0 + 8) * DMODEL + col,
                   oacc[n8][2] * inv1, oacc[n8][3] * inv1);
    }
}

// ---------------- launcher ----------------
extern "C" void kernel_launch(void* const* d_in, const int* in_sizes, int n_in,
                              void* d_out, int out_size) {
    const float* x  = (const float*)d_in[0];
    const float* WQ = (const float*)d_in[1];
    const float* WK = (const float*)d_in[2];
    const float* WV = (const float*)d_in[3];
    const float* WO = (const float*)d_in[4];
    const float* bQ = (const float*)d_in[5];
    const float* bK = (const float*)d_in[6];
    const float* bV = (const float*)d_in[7];
    const float* bO = (const float*)d_in[8];
    float* out = (float*)d_out;

    float* bcat;
    __nv_bfloat16 *xhi, *xlo, *zhi, *zlo, *Wthi, *Wtlo, *WOthi, *WOtlo;
    cudaGetSymbolAddress((void**)&bcat,  g_bcat);
    cudaGetSymbolAddress((void**)&xhi,   g_xhi);
    cudaGetSymbolAddress((void**)&xlo,   g_xlo);
    cudaGetSymbolAddress((void**)&zhi,   g_zhi);
    cudaGetSymbolAddress((void**)&zlo,   g_zlo);
    cudaGetSymbolAddress((void**)&Wthi,  g_Wthi);
    cudaGetSymbolAddress((void**)&Wtlo,  g_Wtlo);
    cudaGetSymbolAddress((void**)&WOthi, g_WOthi);
    cudaGetSymbolAddress((void**)&WOtlo, g_WOtlo);

    cudaFuncSetAttribute(gemm3<0>, cudaFuncAttributeMaxDynamicSharedMemorySize, GSMEM);
    cudaFuncSetAttribute(gemm3<1>, cudaFuncAttributeMaxDynamicSharedMemorySize, GSMEM);
    cudaFuncSetAttribute(attn_mma, cudaFuncAttributeMaxDynamicSharedMemorySize, ATT_SMEM);

    // 1) weight repacks (+rotary table) + input split
    repack_wqkv_rot<<<REP_BLOCKS + (SEQ * 64) / 256, 256>>>(WQ, WK, WV, bQ, bK, bV);
    repack_wo<<<(DMODEL * KDIM + 255) / 256, 256>>>(WO);
    split_f32<<<(SEQ * DMODEL + 255) / 256, 256>>>(x, xhi, xlo, SEQ * DMODEL);

    // 2) QKV projection + fused bias/rotary/split/layout epilogue
    {
        dim3 grid(SEQ / BM, NCOLS / BN);
        gemm3<1><<<grid, 256, GSMEM>>>(xhi, xlo, Wthi, Wtlo, bcat, nullptr, NCOLS);
    }
    // 3) causal flash attention -> zhi/zlo
    {
        dim3 grid(SEQ / 128, NH);
        attn_mma<<<grid, 256, ATT_SMEM>>>();
    }
    // 4) O-projection
    {
        dim3 grid(SEQ / BM, DMODEL / BN);
        gemm3<0><<<grid, 256, GSMEM>>>(zhi, zlo, WOthi, WOtlo, bO, out, DMODEL);
    }
}